// round 8
// baseline (speedup 1.0000x reference)
#include <cuda_runtime.h>
#include <cuda_fp16.h>
#include <math.h>
#include <stdint.h>

// Problem constants
#define BATCH 2
#define SLEN  2048
#define DMODEL 1024
#define NHEAD 16
#define DH    64
#define DFF   2048
#define ROWS_B0   (SLEN)
#define ROWS_ALL  (BATCH*SLEN)

// ---------------- scratch (static device globals; no allocs) ----------------
__device__ __half hh_src[SLEN*DMODEL];
__device__ __half hh_q  [SLEN*DMODEL];
__device__ __half hh_k  [SLEN*DMODEL];
__device__ __half hh_v  [SLEN*DMODEL];
__device__ __half hh_ctx[SLEN*DMODEL];
__device__ float  g_attn[SLEN*DMODEL];
__device__ float  g_x   [ROWS_ALL*DMODEL];
__device__ __half hh_x  [ROWS_ALL*DMODEL];
__device__ __half hh_f1 [ROWS_ALL*DFF];
__device__ float  g_f2  [ROWS_ALL*DMODEL];
// transposed+converted weights ([N][K] half)
__device__ __half hh_wq[DMODEL*DMODEL];
__device__ __half hh_wk[DMODEL*DMODEL];
__device__ __half hh_wv[DMODEL*DMODEL];
__device__ __half hh_wo[DMODEL*DMODEL];
__device__ __half hh_w1[DFF*DMODEL];
__device__ __half hh_w2[DMODEL*DFF];

// ---------------- helpers ----------------------------------------------------
__device__ __forceinline__ uint32_t smem_u32(const void* p) {
    uint32_t a;
    asm("{ .reg .u64 t; cvta.to.shared.u64 t, %1; cvt.u32.u64 %0, t; }"
        : "=r"(a) : "l"(p));
    return a;
}
__device__ __forceinline__ void ldm_x4(unsigned r[4], uint32_t addr) {
    asm volatile("ldmatrix.sync.aligned.m8n8.x4.shared.b16 {%0,%1,%2,%3}, [%4];"
        : "=r"(r[0]), "=r"(r[1]), "=r"(r[2]), "=r"(r[3]) : "r"(addr));
}
__device__ __forceinline__ void ldm_x4_t(unsigned r[4], uint32_t addr) {
    asm volatile("ldmatrix.sync.aligned.m8n8.x4.trans.shared.b16 {%0,%1,%2,%3}, [%4];"
        : "=r"(r[0]), "=r"(r[1]), "=r"(r[2]), "=r"(r[3]) : "r"(addr));
}
__device__ __forceinline__ void mma16(float c[4], const unsigned a[4],
                                      unsigned b0, unsigned b1) {
    asm volatile(
        "mma.sync.aligned.m16n8k16.row.col.f32.f16.f16.f32 "
        "{%0,%1,%2,%3},{%4,%5,%6,%7},{%8,%9},{%0,%1,%2,%3};"
        : "+f"(c[0]), "+f"(c[1]), "+f"(c[2]), "+f"(c[3])
        : "r"(a[0]), "r"(a[1]), "r"(a[2]), "r"(a[3]), "r"(b0), "r"(b1));
}
#define CP_ASYNC16(dst, src) \
    asm volatile("cp.async.cg.shared.global [%0], [%1], 16;" :: "r"(dst), "l"(src))
#define CP_COMMIT() asm volatile("cp.async.commit_group;")
#define CP_WAIT1()  asm volatile("cp.async.wait_group 1;")

// ---------------- fused prep: 6 weight transposes + src f32->f16 -------------
__global__ void __launch_bounds__(256) prep_kernel(
    const float* __restrict__ src,
    const float* __restrict__ wq, const float* __restrict__ wk,
    const float* __restrict__ wv, const float* __restrict__ wo,
    const float* __restrict__ w1, const float* __restrict__ w2,
    __half* __restrict__ hsrc,
    __half* __restrict__ hwq, __half* __restrict__ hwk,
    __half* __restrict__ hwv, __half* __restrict__ hwo,
    __half* __restrict__ hw1, __half* __restrict__ hw2)
{
    __shared__ float t[32][33];
    const int b = blockIdx.x;
    const float* in; __half* outp; int R, C, bxi, byi;
    if (b < 4096) {
        int seg = b >> 10, lb = b & 1023;
        in   = (seg == 0) ? wq  : (seg == 1) ? wk  : (seg == 2) ? wv  : wo;
        outp = (seg == 0) ? hwq : (seg == 1) ? hwk : (seg == 2) ? hwv : hwo;
        R = 1024; C = 1024; bxi = lb & 31; byi = lb >> 5;
    } else if (b < 6144) {
        int lb = b - 4096; in = w1; outp = hw1; R = 1024; C = 2048;
        bxi = lb & 63; byi = lb >> 6;
    } else if (b < 8192) {
        int lb = b - 6144; in = w2; outp = hw2; R = 2048; C = 1024;
        bxi = lb & 31; byi = lb >> 5;
    } else {
        int lb = b - 8192;
        int i = (lb * 256 + threadIdx.x) * 4;
        float4 v = *(const float4*)(src + i);
        *(__half2*)(hsrc + i)     = __floats2half2_rn(v.x, v.y);
        *(__half2*)(hsrc + i + 2) = __floats2half2_rn(v.z, v.w);
        return;
    }
    const int tx = threadIdx.x & 31, ty = threadIdx.x >> 5;
    const int bx = bxi * 32, by = byi * 32;
    #pragma unroll
    for (int i = ty; i < 32; i += 8)
        t[i][tx] = in[(size_t)(by + i) * C + bx + tx];
    __syncthreads();
    #pragma unroll
    for (int i = ty; i < 32; i += 8)
        outp[(size_t)(bx + i) * R + by + tx] = __float2half(t[tx][i]);
}

// ---------------- fp16 tensor-core GEMM (3-stage, 1 sync/iter) ---------------
// C[M,N] = A[M,K] @ Bt[N,K]^T + bias (+optional exact GELU)
// 128x128 tile, K-tile 64, 256 thr = 8 warps (4M x 2N), warp tile 32x64.
#define HST 72                      // halves per smem row (144B)
#define OP_BYTES (128*HST*2)        // 18432 per operand per stage
#define GEMM_SMEM (6*OP_BYTES)      // 3 stages * (A+B) = 110592

__global__ void __launch_bounds__(256) gemm_fp16_kernel(
    const __half* __restrict__ A,
    const __half* __restrict__ B0, const __half* __restrict__ B1, const __half* __restrict__ B2,
    const float* __restrict__ bias0, const float* __restrict__ bias1, const float* __restrict__ bias2,
    float* __restrict__ C0, float* __restrict__ C1, float* __restrict__ C2,
    __half* __restrict__ H0, __half* __restrict__ H1, __half* __restrict__ H2,
    int M, int N, int K, int gelu)
{
    extern __shared__ __half sm[];
    const int z = blockIdx.z;
    const __half* Bt  = (z == 0) ? B0 : (z == 1) ? B1 : B2;
    const float* bias = (z == 0) ? bias0 : (z == 1) ? bias1 : bias2;
    float*  C = (z == 0) ? C0 : (z == 1) ? C1 : C2;
    __half* H = (z == 0) ? H0 : (z == 1) ? H1 : H2;

    const int tid = threadIdx.x, lane = tid & 31, warp = tid >> 5;
    const int wm = warp >> 1, wn = warp & 1;
    const int row0 = blockIdx.y * 128, col0 = blockIdx.x * 128;

    uint32_t smb = smem_u32(sm);
    uint32_t aB[3] = { smb, smb + 2 * OP_BYTES, smb + 4 * OP_BYTES };
    uint32_t bB[3] = { smb + OP_BYTES, smb + 3 * OP_BYTES, smb + 5 * OP_BYTES };

    float acc[2][8][4];
    #pragma unroll
    for (int mt = 0; mt < 2; ++mt)
        #pragma unroll
        for (int nt = 0; nt < 8; ++nt)
            #pragma unroll
            for (int i = 0; i < 4; ++i) acc[mt][nt][i] = 0.f;

    const int aRow = wm * 32 + (lane & 15);
    const int aCol = (lane >> 4) * 8;
    const int quad = lane >> 3, ql = lane & 7;
    const int bRowB = wn * 64 + ((quad >> 1) << 3) + ql;
    const int bColB = (quad & 1) * 8;

    const int nk = K >> 6;

    // prologue: stages 0,1
    #pragma unroll 1
    for (int p = 0; p < 2; ++p) {
        int k0 = p * 64;
        #pragma unroll
        for (int i = 0; i < 4; ++i) {
            int idx = tid + i * 256;
            int r = idx >> 3, ch = idx & 7;
            CP_ASYNC16(aB[p] + r * 144 + ch * 16, A  + (size_t)(row0 + r) * K + k0 + ch * 8);
            CP_ASYNC16(bB[p] + r * 144 + ch * 16, Bt + (size_t)(col0 + r) * K + k0 + ch * 8);
        }
        CP_COMMIT();
    }

    int ldbuf = 2;   // buffer for stage s+2 at iter s: (s+2)%3, starts at 2
    for (int s = 0; s < nk; ++s) {
        CP_WAIT1();          // stage s landed
        __syncthreads();     // all warps past compute of stage s-1 -> buf (s+2)%3 free

        if (s + 2 < nk) {
            int k0 = (s + 2) * 64;
            #pragma unroll
            for (int i = 0; i < 4; ++i) {
                int idx = tid + i * 256;
                int r = idx >> 3, ch = idx & 7;
                CP_ASYNC16(aB[ldbuf] + r * 144 + ch * 16, A  + (size_t)(row0 + r) * K + k0 + ch * 8);
                CP_ASYNC16(bB[ldbuf] + r * 144 + ch * 16, Bt + (size_t)(col0 + r) * K + k0 + ch * 8);
            }
        }
        CP_COMMIT();
        if (++ldbuf == 3) ldbuf = 0;

        const int buf = s % 3;
        #pragma unroll
        for (int ks = 0; ks < 4; ++ks) {
            unsigned af0[4], af1[4];
            ldm_x4(af0, aB[buf] + aRow * 144 + (ks * 16 + aCol) * 2);
            ldm_x4(af1, aB[buf] + (aRow + 16) * 144 + (ks * 16 + aCol) * 2);
            #pragma unroll
            for (int pr = 0; pr < 4; ++pr) {
                unsigned bf[4];
                ldm_x4(bf, bB[buf] + (bRowB + pr * 16) * 144 + (ks * 16 + bColB) * 2);
                mma16(acc[0][2 * pr],     af0, bf[0], bf[1]);
                mma16(acc[0][2 * pr + 1], af0, bf[2], bf[3]);
                mma16(acc[1][2 * pr],     af1, bf[0], bf[1]);
                mma16(acc[1][2 * pr + 1], af1, bf[2], bf[3]);
            }
        }
    }

    const int g = lane >> 2, c4 = lane & 3;
    #pragma unroll
    for (int mt = 0; mt < 2; ++mt) {
        int r = row0 + wm * 32 + mt * 16 + g;
        #pragma unroll
        for (int nt = 0; nt < 8; ++nt) {
            int cc = col0 + wn * 64 + nt * 8 + 2 * c4;
            float bz0 = bias[cc], bz1 = bias[cc + 1];
            float v0 = acc[mt][nt][0] + bz0;
            float v1 = acc[mt][nt][1] + bz1;
            float v2 = acc[mt][nt][2] + bz0;
            float v3 = acc[mt][nt][3] + bz1;
            if (gelu) {
                v0 = 0.5f * v0 * (1.f + erff(v0 * 0.70710678118654752f));
                v1 = 0.5f * v1 * (1.f + erff(v1 * 0.70710678118654752f));
                v2 = 0.5f * v2 * (1.f + erff(v2 * 0.70710678118654752f));
                v3 = 0.5f * v3 * (1.f + erff(v3 * 0.70710678118654752f));
            }
            if (C) {
                *(float2*)(C + (size_t)r * N + cc)       = make_float2(v0, v1);
                *(float2*)(C + (size_t)(r + 8) * N + cc) = make_float2(v2, v3);
            }
            if (H) {
                *(__half2*)(H + (size_t)r * N + cc)       = __floats2half2_rn(v0, v1);
                *(__half2*)(H + (size_t)(r + 8) * N + cc) = __floats2half2_rn(v2, v3);
            }
        }
    }
}

// ---------------- fp16 flash attention (batch 0), BQ=128, 3-stage ------------
// grid (SLEN/128, NHEAD), 256 thr = 8 warps, warp owns 16 q-rows. BK=64.
// dynamic smem (halves): ks0|ks1|ks2|vs0|vs1|vs2|ps(128 rows)
#define FL_PS  (6*64*HST)
#define FL_SMEM ((6*64*HST + 128*HST) * 2)   // 73728 bytes

__global__ void __launch_bounds__(256) flash_fp16_kernel(
    const __half* __restrict__ Q, const __half* __restrict__ K,
    const __half* __restrict__ V, __half* __restrict__ O)
{
    extern __shared__ __half fsm[];
    const int h = blockIdx.y, q0 = blockIdx.x * 128;
    const int tid = threadIdx.x, lane = tid & 31, warp = tid >> 5;
    const int wrow = warp * 16;
    const int g = lane >> 2, c4 = lane & 3;

    uint32_t smb = smem_u32(fsm);
    uint32_t ksb[3] = { smb, smb + 64*HST*2, smb + 2*64*HST*2 };
    uint32_t vsb[3] = { smb + 3*64*HST*2, smb + 4*64*HST*2, smb + 5*64*HST*2 };
    uint32_t psb = smb + FL_PS * 2;
    __half* Ps = fsm + FL_PS;

    const __half* Qg = Q + (size_t)q0 * DMODEL + h * DH;
    const __half* Kg = K + h * DH;
    const __half* Vg = V + h * DH;

    // stage Q tile (128x64) into Ps, then per-warp A-frags to registers
    #pragma unroll
    for (int i = 0; i < 4; ++i) {
        int idx = tid + i * 256;
        int r = idx >> 3, ch = idx & 7;
        *(uint4*)(Ps + r * HST + ch * 8) = *(const uint4*)(Qg + (size_t)r * DMODEL + ch * 8);
    }
    __syncthreads();
    const int aRow = wrow + (lane & 15);
    const int aCol = (lane >> 4) * 8;
    unsigned qa[4][4];
    #pragma unroll
    for (int ks = 0; ks < 4; ++ks)
        ldm_x4(qa[ks], psb + aRow * 144 + (ks * 16 + aCol) * 2);

    float oacc[8][4];
    #pragma unroll
    for (int nt = 0; nt < 8; ++nt)
        #pragma unroll
        for (int i = 0; i < 4; ++i) oacc[nt][i] = 0.f;
    float m0 = -1e30f, m1 = -1e30f, l0 = 0.f, l1 = 0.f;

    const int quad = lane >> 3, ql = lane & 7;
    const int bRowS = ((quad >> 1) << 3) + ql;
    const int bColS = (quad & 1) * 8;
    const int vRow  = (quad & 1) * 8 + ql;
    const int vCol  = (quad >> 1) * 8;

    // prologue K/V loads (stages 0,1)
    #pragma unroll 1
    for (int p = 0; p < 2; ++p) {
        int s0 = p * 64;
        #pragma unroll
        for (int i = 0; i < 4; ++i) {
            int idx = tid + i * 256;
            if (idx < 512) {
                int r = idx >> 3, ch = idx & 7;
                CP_ASYNC16(ksb[p] + r * 144 + ch * 16, Kg + (size_t)(s0 + r) * DMODEL + ch * 8);
            } else {
                int j = idx - 512; int r = j >> 3, ch = j & 7;
                CP_ASYNC16(vsb[p] + r * 144 + ch * 16, Vg + (size_t)(s0 + r) * DMODEL + ch * 8);
            }
        }
        CP_COMMIT();
    }

    int ldbuf = 2;
    for (int kt = 0; kt < SLEN / 64; ++kt) {
        CP_WAIT1();
        __syncthreads();

        if (kt + 2 < SLEN / 64) {
            int s0 = (kt + 2) * 64;
            #pragma unroll
            for (int i = 0; i < 4; ++i) {
                int idx = tid + i * 256;
                if (idx < 512) {
                    int r = idx >> 3, ch = idx & 7;
                    CP_ASYNC16(ksb[ldbuf] + r * 144 + ch * 16, Kg + (size_t)(s0 + r) * DMODEL + ch * 8);
                } else {
                    int j = idx - 512; int r = j >> 3, ch = j & 7;
                    CP_ASYNC16(vsb[ldbuf] + r * 144 + ch * 16, Vg + (size_t)(s0 + r) * DMODEL + ch * 8);
                }
            }
        }
        CP_COMMIT();
        if (++ldbuf == 3) ldbuf = 0;

        const int buf = kt % 3;

        // S = Q @ K^T
        float sacc[8][4];
        #pragma unroll
        for (int nt = 0; nt < 8; ++nt)
            #pragma unroll
            for (int i = 0; i < 4; ++i) sacc[nt][i] = 0.f;
        #pragma unroll
        for (int ks = 0; ks < 4; ++ks) {
            #pragma unroll
            for (int pr = 0; pr < 4; ++pr) {
                unsigned bf[4];
                ldm_x4(bf, ksb[buf] + (bRowS + pr * 16) * 144 + (ks * 16 + bColS) * 2);
                mma16(sacc[2 * pr],     qa[ks], bf[0], bf[1]);
                mma16(sacc[2 * pr + 1], qa[ks], bf[2], bf[3]);
            }
        }

        // online softmax (rows g and g+8 of the warp's 16)
        float mx0 = -1e30f, mx1 = -1e30f;
        #pragma unroll
        for (int nt = 0; nt < 8; ++nt) {
            mx0 = fmaxf(mx0, fmaxf(sacc[nt][0], sacc[nt][1]));
            mx1 = fmaxf(mx1, fmaxf(sacc[nt][2], sacc[nt][3]));
        }
        mx0 = fmaxf(mx0, __shfl_xor_sync(0xffffffffu, mx0, 1));
        mx0 = fmaxf(mx0, __shfl_xor_sync(0xffffffffu, mx0, 2));
        mx1 = fmaxf(mx1, __shfl_xor_sync(0xffffffffu, mx1, 1));
        mx1 = fmaxf(mx1, __shfl_xor_sync(0xffffffffu, mx1, 2));
        float m0n = fmaxf(m0, mx0 * 0.125f);
        float m1n = fmaxf(m1, mx1 * 0.125f);
        float corr0 = __expf(m0 - m0n);
        float corr1 = __expf(m1 - m1n);

        float sum0 = 0.f, sum1 = 0.f;
        #pragma unroll
        for (int nt = 0; nt < 8; ++nt) {
            float p00 = __expf(sacc[nt][0] * 0.125f - m0n);
            float p01 = __expf(sacc[nt][1] * 0.125f - m0n);
            float p10 = __expf(sacc[nt][2] * 0.125f - m1n);
            float p11 = __expf(sacc[nt][3] * 0.125f - m1n);
            sum0 += p00 + p01;
            sum1 += p10 + p11;
            *(__half2*)(Ps + (wrow + g)     * HST + nt * 8 + 2 * c4) = __floats2half2_rn(p00, p01);
            *(__half2*)(Ps + (wrow + g + 8) * HST + nt * 8 + 2 * c4) = __floats2half2_rn(p10, p11);
        }
        sum0 += __shfl_xor_sync(0xffffffffu, sum0, 1);
        sum0 += __shfl_xor_sync(0xffffffffu, sum0, 2);
        sum1 += __shfl_xor_sync(0xffffffffu, sum1, 1);
        sum1 += __shfl_xor_sync(0xffffffffu, sum1, 2);
        m0 = m0n; m1 = m1n;
        l0 = l0 * corr0 + sum0;
        l1 = l1 * corr1 + sum1;
        #pragma unroll
        for (int nt = 0; nt < 8; ++nt) {
            oacc[nt][0] *= corr0; oacc[nt][1] *= corr0;
            oacc[nt][2] *= corr1; oacc[nt][3] *= corr1;
        }
        __syncwarp();

        // O += P @ V   (P rows warp-local in Ps)
        #pragma unroll
        for (int ks = 0; ks < 4; ++ks) {
            unsigned pf[4];
            ldm_x4(pf, psb + aRow * 144 + (ks * 16 + aCol) * 2);
            #pragma unroll
            for (int pr = 0; pr < 4; ++pr) {
                unsigned bf[4];
                ldm_x4_t(bf, vsb[buf] + (vRow + ks * 16) * 144 + (vCol + pr * 16) * 2);
                mma16(oacc[2 * pr],     pf, bf[0], bf[1]);
                mma16(oacc[2 * pr + 1], pf, bf[2], bf[3]);
            }
        }
    }

    float i0 = 1.f / l0, i1 = 1.f / l1;
    #pragma unroll
    for (int nt = 0; nt < 8; ++nt) {
        int cc = h * DH + nt * 8 + 2 * c4;
        *(__half2*)(O + (size_t)(q0 + wrow + g)     * DMODEL + cc) =
            __floats2half2_rn(oacc[nt][0] * i0, oacc[nt][1] * i0);
        *(__half2*)(O + (size_t)(q0 + wrow + g + 8) * DMODEL + cc) =
            __floats2half2_rn(oacc[nt][2] * i1, oacc[nt][3] * i1);
    }
}

// ---------------- fused residual-add + LayerNorm (+ optional half copy) ------
__global__ void __launch_bounds__(256) add_ln_kernel(
    const float* __restrict__ X, const float* __restrict__ Y,
    const float* __restrict__ g, const float* __restrict__ b,
    float* __restrict__ out, __half* __restrict__ outh, int ymod)
{
    const int row = blockIdx.x;
    const int tid = threadIdx.x;
    const float* xr = X + (size_t)row * DMODEL;
    const float* yr = Y + (size_t)(row % ymod) * DMODEL;

    float4 xv = *(const float4*)(xr + tid * 4);
    float4 yv = *(const float4*)(yr + tid * 4);
    float v0 = xv.x + yv.x, v1 = xv.y + yv.y, v2 = xv.z + yv.z, v3 = xv.w + yv.w;

    float sum = v0 + v1 + v2 + v3;
    float sq  = v0*v0 + v1*v1 + v2*v2 + v3*v3;
    #pragma unroll
    for (int off = 16; off; off >>= 1) {
        sum += __shfl_xor_sync(0xffffffffu, sum, off);
        sq  += __shfl_xor_sync(0xffffffffu, sq,  off);
    }
    __shared__ float ssum[8], ssq[8];
    int w = tid >> 5, lane = tid & 31;
    if (lane == 0) { ssum[w] = sum; ssq[w] = sq; }
    __syncthreads();
    if (tid == 0) {
        float ts = 0.f, tq = 0.f;
        #pragma unroll
        for (int i = 0; i < 8; ++i) { ts += ssum[i]; tq += ssq[i]; }
        ssum[0] = ts; ssq[0] = tq;
    }
    __syncthreads();
    const float mu   = ssum[0] * (1.f / DMODEL);
    const float var  = ssq[0] * (1.f / DMODEL) - mu * mu;
    const float rstd = rsqrtf(var + 1e-5f);

    int cc = tid * 4;
    float4 gv = *(const float4*)(g + cc);
    float4 bv = *(const float4*)(b + cc);
    float4 o;
    o.x = (v0 - mu) * rstd * gv.x + bv.x;
    o.y = (v1 - mu) * rstd * gv.y + bv.y;
    o.z = (v2 - mu) * rstd * gv.z + bv.z;
    o.w = (v3 - mu) * rstd * gv.w + bv.w;
    *(float4*)(out + (size_t)row * DMODEL + cc) = o;
    if (outh) {
        *(__half2*)(outh + (size_t)row * DMODEL + cc)     = __floats2half2_rn(o.x, o.y);
        *(__half2*)(outh + (size_t)row * DMODEL + cc + 2) = __floats2half2_rn(o.z, o.w);
    }
}

// ---------------- launch -----------------------------------------------------
extern "C" void kernel_launch(void* const* d_in, const int* in_sizes, int n_in,
                              void* d_out, int out_size)
{
    const float* src    = (const float*)d_in[0];
    const float* w_q    = (const float*)d_in[1];
    const float* b_q    = (const float*)d_in[2];
    const float* w_k    = (const float*)d_in[3];
    const float* b_k    = (const float*)d_in[4];
    const float* w_v    = (const float*)d_in[5];
    const float* b_v    = (const float*)d_in[6];
    const float* w_out  = (const float*)d_in[7];
    const float* b_out  = (const float*)d_in[8];
    const float* ln1_g  = (const float*)d_in[9];
    const float* ln1_b  = (const float*)d_in[10];
    const float* ln2_g  = (const float*)d_in[11];
    const float* ln2_b  = (const float*)d_in[12];
    const float* ffn_w1 = (const float*)d_in[13];
    const float* ffn_b1 = (const float*)d_in[14];
    const float* ffn_w2 = (const float*)d_in[15];
    const float* ffn_b2 = (const float*)d_in[16];
    float* out = (float*)d_out;

    __half *psrc, *pq, *pk, *pv, *pctx, *pxh, *pf1;
    __half *pwq, *pwk, *pwv, *pwo, *pw1, *pw2;
    float *pattn, *px, *pf2;
    cudaGetSymbolAddress((void**)&psrc, hh_src);
    cudaGetSymbolAddress((void**)&pq,   hh_q);
    cudaGetSymbolAddress((void**)&pk,   hh_k);
    cudaGetSymbolAddress((void**)&pv,   hh_v);
    cudaGetSymbolAddress((void**)&pctx, hh_ctx);
    cudaGetSymbolAddress((void**)&pxh,  hh_x);
    cudaGetSymbolAddress((void**)&pf1,  hh_f1);
    cudaGetSymbolAddress((void**)&pwq,  hh_wq);
    cudaGetSymbolAddress((void**)&pwk,  hh_wk);
    cudaGetSymbolAddress((void**)&pwv,  hh_wv);
    cudaGetSymbolAddress((void**)&pwo,  hh_wo);
    cudaGetSymbolAddress((void**)&pw1,  hh_w1);
    cudaGetSymbolAddress((void**)&pw2,  hh_w2);
    cudaGetSymbolAddress((void**)&pattn, g_attn);
    cudaGetSymbolAddress((void**)&px,    g_x);
    cudaGetSymbolAddress((void**)&pf2,   g_f2);

    cudaFuncSetAttribute(gemm_fp16_kernel,
                         cudaFuncAttributeMaxDynamicSharedMemorySize, GEMM_SMEM);
    cudaFuncSetAttribute(flash_fp16_kernel,
                         cudaFuncAttributeMaxDynamicSharedMemorySize, FL_SMEM);

    // 1) fused prep: all weight transposes + src convert
    prep_kernel<<<10240, 256>>>(src, w_q, w_k, w_v, w_out, ffn_w1, ffn_w2,
                                psrc, pwq, pwk, pwv, pwo, pw1, pw2);

    // 2) fused QKV projections (batch 0), grid.z = 3, half outputs
    gemm_fp16_kernel<<<dim3(DMODEL/128, ROWS_B0/128, 3), 256, GEMM_SMEM>>>(
        psrc, pwq, pwk, pwv, b_q, b_k, b_v,
        (float*)0, (float*)0, (float*)0, pq, pk, pv,
        ROWS_B0, DMODEL, DMODEL, 0);

    // 3) attention (batch 0), BQ=128
    flash_fp16_kernel<<<dim3(SLEN/128, NHEAD), 256, FL_SMEM>>>(pq, pk, pv, pctx);

    // 4) output projection -> f32
    gemm_fp16_kernel<<<dim3(DMODEL/128, ROWS_B0/128, 1), 256, GEMM_SMEM>>>(
        pctx, pwo, pwo, pwo, b_out, b_out, b_out,
        pattn, pattn, pattn, (__half*)0, (__half*)0, (__half*)0,
        ROWS_B0, DMODEL, DMODEL, 0);

    // 5) x = LN1(src + attn_out[0] broadcast)  -> f32 + half
    add_ln_kernel<<<ROWS_ALL, 256>>>(src, pattn, ln1_g, ln1_b, px, pxh, SLEN);

    // 6) FFN1 (+GELU) -> half
    gemm_fp16_kernel<<<dim3(DFF/128, ROWS_ALL/128, 1), 256, GEMM_SMEM>>>(
        pxh, pw1, pw1, pw1, ffn_b1, ffn_b1, ffn_b1,
        (float*)0, (float*)0, (float*)0, pf1, pf1, pf1,
        ROWS_ALL, DFF, DMODEL, 1);

    // 7) FFN2 -> f32
    gemm_fp16_kernel<<<dim3(DMODEL/128, ROWS_ALL/128, 1), 256, GEMM_SMEM>>>(
        pf1, pw2, pw2, pw2, ffn_b2, ffn_b2, ffn_b2,
        pf2, pf2, pf2, (__half*)0, (__half*)0, (__half*)0,
        ROWS_ALL, DMODEL, DFF, 0);

    // 8) out = LN2(x + ffn)
    add_ln_kernel<<<ROWS_ALL, 256>>>(px, pf2, ln2_g, ln2_b, out, (__half*)0, ROWS_ALL);
}